// round 5
// baseline (speedup 1.0000x reference)
#include <cuda_runtime.h>
#include <cuda_fp16.h>
#include <math.h>
#include <stdint.h>

// Problem constants
#define HW     36864          // 192*192
#define CIN    64
#define BS     2
#define NQ     4096
#define COUT   69

// Tiling
#define QT     128            // queries per block
#define CK     64             // m per chunk
#define NSEG   21             // grid 7*21*2 = 294 ~= 148 SM * occ2
#define TCH    (HW / CK)      // 576 total chunks
#define MAXV   896            // 7 * 128 slots
#define PSTR   144            // P/V shared row stride bytes (72 fp16)
#define NCH    80             // useful V rows: 64 fea + 3 sq + pad-to-tile
#define VROWS  88             // allocated V rows (ldsm over-read pad)
#define VSZ    (VROWS * PSTR)
#define PSZ    (QT * PSTR)

struct QParam {
    int nv;
    int rowstart[65];
    int umin[64];
};

// Split-K partials
__device__ __align__(16) float g_sumw[BS][NSEG][MAXV];
__device__ __align__(16) float g_swc [BS][NSEG][MAXV];
__device__ __align__(16) float g_acc [BS][NSEG][MAXV][NCH];

// ---------------- PTX helpers ----------------
__device__ __forceinline__ uint32_t smem_u32(const void* p) {
    uint32_t a;
    asm("{ .reg .u64 t; cvta.to.shared.u64 t, %1; cvt.u32.u64 %0, t; }"
        : "=r"(a) : "l"(p));
    return a;
}

#define FMA2(d, a, b, c) asm("fma.rn.f32x2 %0, %1, %2, %3;" : "=l"(d) : "l"(a), "l"(b), "l"(c))
#define MUL2(d, a, b)    asm("mul.rn.f32x2 %0, %1, %2;"     : "=l"(d) : "l"(a), "l"(b))
#define ADD2(d, a, b)    asm("add.rn.f32x2 %0, %1, %2;"     : "=l"(d) : "l"(a), "l"(b))

__device__ __forceinline__ unsigned long long pk2(float lo, float hi) {
    unsigned long long r;
    asm("mov.b64 %0, {%1, %2};" : "=l"(r) : "f"(lo), "f"(hi));
    return r;
}
__device__ __forceinline__ void upk2(unsigned long long v, float& lo, float& hi) {
    asm("mov.b64 {%0, %1}, %2;" : "=f"(lo), "=f"(hi) : "l"(v));
}
__device__ __forceinline__ float ex2f(float x) {
    float r; asm("ex2.approx.ftz.f32 %0, %1;" : "=f"(r) : "f"(x)); return r;
}
__device__ __forceinline__ uint32_t cvt_f16x2(float lo, float hi) {
    uint32_t r; asm("cvt.rn.f16x2.f32 %0, %1, %2;" : "=r"(r) : "f"(hi), "f"(lo)); return r;
}
__device__ __forceinline__ void ldsm_x4(uint32_t& r0, uint32_t& r1, uint32_t& r2,
                                        uint32_t& r3, uint32_t addr) {
    asm volatile("ldmatrix.sync.aligned.m8n8.x4.shared.b16 {%0,%1,%2,%3}, [%4];"
                 : "=r"(r0), "=r"(r1), "=r"(r2), "=r"(r3) : "r"(addr));
}
__device__ __forceinline__ void mma16816(float* d, const uint32_t* a,
                                         uint32_t b0, uint32_t b1) {
    asm volatile("mma.sync.aligned.m16n8k16.row.col.f32.f16.f16.f32 "
                 "{%0,%1,%2,%3}, {%4,%5,%6,%7}, {%8,%9}, {%0,%1,%2,%3};"
                 : "+f"(d[0]), "+f"(d[1]), "+f"(d[2]), "+f"(d[3])
                 : "r"(a[0]), "r"(a[1]), "r"(a[2]), "r"(a[3]), "r"(b0), "r"(b1));
}

// ---------------- query helpers ----------------
__device__ __forceinline__ bool q_valid(int u, int v) {
    int du = 2 * u - 63, dv = 2 * v - 63;
    return du * du + dv * dv < 1024;
}

__device__ __forceinline__ int slot_to_qidx(const QParam& qp, int slot) {
    if (slot >= qp.nv) return -1;
    int lo = 0, hi = 64;
    while (hi - lo > 1) {
        int mid = (lo + hi) >> 1;
        if (qp.rowstart[mid] <= slot) lo = mid; else hi = mid;
    }
    return lo * 64 + qp.umin[lo] + (slot - qp.rowstart[lo]);
}

__device__ __forceinline__ void qn_of(int qidx, float& x, float& y, float& z) {
    if (qidx < 0) { x = y = z = 0.f; return; }
    int v = qidx >> 6, u = qidx & 63;
    if (!q_valid(u, v)) { x = y = z = 0.f; return; }
    float p =  4.0f * ((u + 0.5f) * (1.0f / 64.0f) - 0.5f);
    float q = -4.0f * ((v + 0.5f) * (1.0f / 64.0f) - 0.5f);
    float r2 = p * p + q * q;
    float inv = 1.0f / (1.0f + r2);
    x = 2.0f * p * inv;
    y = 2.0f * q * inv;
    z = (1.0f - r2) * inv;
}

// -------------------------------------------------------------------------
// Main kernel: grid (7, NSEG, BS), 256 threads, occ 2.
// Software-pipelined, ONE __syncthreads per chunk:
//   iter ci: STS(regs ci) -> bufs[ci%3]; LDG(ci+1) -> regs; sync;
//            wgen(ci) -> P[ci&1]; mma(ci-1) on P[(ci-1)&1] / V[(ci-1)%3]
// -------------------------------------------------------------------------
__global__ __launch_bounds__(256, 2)
void k_main(const float* __restrict__ fea, const float* __restrict__ nrm,
            const float* __restrict__ msk, const float* __restrict__ lqn,
            QParam qp)
{
    __shared__ __align__(16) float4 pA[3][32];        // {nx0,nx1,ny0,ny1} per m-pair
    __shared__ __align__(16) float4 pB[3][32];        // {nz0,nz1,mk0,mk1}
    __shared__ __align__(16) char   P_sh[2][PSZ];     // 128 x 72 fp16
    __shared__ __align__(16) char   V_sh[3][VSZ];     // 88 x 72 fp16

    const int t = threadIdx.x;
    const int wid = t >> 5, lid = t & 31;
    const int qb = blockIdx.x, seg = blockIdx.y, b = blockIdx.z;
    const int slot0 = qb * QT;

    const uint32_t sbP = smem_u32(P_sh);
    const uint32_t sbV = smem_u32(V_sh);

    const float scale = __expf(lqn[0]) * 0.57735026918962576f;
    const float off   = 1.0f - 8.0f / scale;
    const float k2c   = scale * 1.44269504088896341f;
    const unsigned long long kk2 = pk2(k2c, k2c);
    const unsigned long long bb2 = pk2(-k2c * off, -k2c * off);

    const float* nb = nrm + (size_t)b * 3 * HW;
    const float* fb = fea + (size_t)b * CIN * HW;
    const float* mb = msk + (size_t)b * HW;

    // w-gen role: 2 queries x 8 pairs per thread
    const int q0w = (t >> 2) * 2;
    const int ph  = t & 3;
    float qx0, qy0, qz0, qx1, qy1, qz1;
    qn_of(slot_to_qidx(qp, slot0 + q0w),     qx0, qy0, qz0);
    qn_of(slot_to_qidx(qp, slot0 + q0w + 1), qx1, qy1, qz1);
    const unsigned long long qxx[2] = { pk2(qx0, qx0), pk2(qx1, qx1) };
    const unsigned long long qyy[2] = { pk2(qy0, qy0), pk2(qy1, qy1) };
    const unsigned long long qzz[2] = { pk2(qz0, qz0), pk2(qz1, qz1) };

    // V-load role
    const int vc = t >> 2, vmq = (t & 3) * 16;
    // normals/mask role: 1 value per thread
    const int nd = t >> 6, nm = t & 63;

    // mma role: 4 q-tiles of 32, 2 balanced ch groups of 40
    const int wq = (wid & 3) * 32;
    const int cg = wid >> 2;
    const int wc = cg * 40;
    const uint32_t aOff = (uint32_t)((wq + (lid & 15)) * PSTR + (lid >> 4) * 16);
    const uint32_t bOff = (uint32_t)((wc + (lid & 15)) * PSTR + (lid >> 4) * 16);

    float acc[2][5][4];
    #pragma unroll
    for (int i = 0; i < 2; i++)
        #pragma unroll
        for (int j = 0; j < 5; j++)
            #pragma unroll
            for (int k = 0; k < 4; k++) acc[i][j][k] = 0.f;

    unsigned long long a_sumw[2] = {0ull, 0ull}, a_swc[2] = {0ull, 0ull};

    // zero V pad rows 67..87 in all 3 buffers (never overwritten)
    for (int i = t; i < 3 * 21 * 36; i += 256) {
        int buf = i / (21 * 36);
        int r   = (i - buf * 21 * 36) / 36;
        int wd  = i % 36;
        *(uint32_t*)(V_sh[buf] + (67 + r) * PSTR + wd * 4) = 0u;
    }

    const int c0 = (seg * TCH) / NSEG;
    const int c1 = ((seg + 1) * TCH) / NSEG;

    // prefetch registers
    float4 pf[4];
    float  pfn;

    {   // prologue LDG for chunk c0
        const int mb0 = c0 * CK;
        const float* src = fb + (size_t)vc * HW + mb0 + vmq;
        #pragma unroll
        for (int k = 0; k < 4; k++) pf[k] = *(const float4*)(src + k * 4);
        pfn = (t < 192) ? nb[(size_t)nd * HW + mb0 + nm] : mb[mb0 + nm];
    }

    for (int ci = c0; ci < c1; ci++) {
        const int jv = ci % 3;          // V/normals buffer
        const int jp = ci & 1;          // P buffer

        // ---- STS: prefetched chunk ci data into bufs[jv] ----
        {
            char* vrow = V_sh[jv] + vc * PSTR + vmq * 2;
            #pragma unroll
            for (int k = 0; k < 4; k++) {
                const float4 v = pf[k];
                *(uint2*)(vrow + k * 8) =
                    make_uint2(cvt_f16x2(v.x, v.y), cvt_f16x2(v.z, v.w));
                if (vc >= 61) {   // squares -> rows 64..66
                    *(uint2*)(vrow + 3 * PSTR + k * 8) =
                        make_uint2(cvt_f16x2(v.x * v.x, v.y * v.y),
                                   cvt_f16x2(v.z * v.z, v.w * v.w));
                }
            }
            if (t < 192) {
                if (nd == 0)      ((float*)&pA[jv][nm >> 1])[nm & 1] = pfn;
                else if (nd == 1) ((float*)&pA[jv][nm >> 1])[2 + (nm & 1)] = pfn;
                else              ((float*)&pB[jv][nm >> 1])[nm & 1] = pfn;
            } else {
                ((float*)&pB[jv][nm >> 1])[2 + (nm & 1)] = pfn;
            }
        }

        // ---- LDG chunk ci+1 (latency hidden behind sync+wgen+mma) ----
        if (ci + 1 < c1) {
            const int mb0 = (ci + 1) * CK;
            const float* src = fb + (size_t)vc * HW + mb0 + vmq;
            #pragma unroll
            for (int k = 0; k < 4; k++) pf[k] = *(const float4*)(src + k * 4);
            pfn = (t < 192) ? nb[(size_t)nd * HW + mb0 + nm] : mb[mb0 + nm];
        }

        __syncthreads();

        // ---- wgen(ci): 2 queries per pair-load -> P[jp] ----
        {
            uint32_t wst[2][8];
            #pragma unroll
            for (int k = 0; k < 8; k++) {
                const int p = ph * 8 + k;
                const ulonglong2 uab = *(const ulonglong2*)(&pA[jv][p]);
                const ulonglong2 ucd = *(const ulonglong2*)(&pB[jv][p]);
                #pragma unroll
                for (int qi = 0; qi < 2; qi++) {
                    unsigned long long c2, a2, w2;
                    MUL2(c2, uab.x, qxx[qi]);
                    FMA2(c2, uab.y, qyy[qi], c2);
                    FMA2(c2, ucd.x, qzz[qi], c2);
                    FMA2(a2, c2, kk2, bb2);
                    float a0, a1;
                    upk2(a2, a0, a1);
                    w2 = pk2(ex2f(a0), ex2f(a1));
                    MUL2(w2, w2, ucd.y);
                    ADD2(a_sumw[qi], a_sumw[qi], w2);
                    FMA2(a_swc[qi], w2, c2, a_swc[qi]);
                    float w0, w1;
                    upk2(w2, w0, w1);
                    wst[qi][k] = cvt_f16x2(w0, w1);
                }
            }
            #pragma unroll
            for (int qi = 0; qi < 2; qi++) {
                char* prow = P_sh[jp] + (q0w + qi) * PSTR + ph * 32;
                *(uint4*)(prow)      = make_uint4(wst[qi][0], wst[qi][1], wst[qi][2], wst[qi][3]);
                *(uint4*)(prow + 16) = make_uint4(wst[qi][4], wst[qi][5], wst[qi][6], wst[qi][7]);
            }
        }

        // ---- mma(ci-1): P[jp^1] x V[(ci-1)%3] ----
        if (ci > c0) {
            const uint32_t aAddr = sbP + (uint32_t)((jp ^ 1) * PSZ) + aOff;
            const uint32_t bAddr = sbV + (uint32_t)(((ci - 1) % 3) * VSZ) + bOff;
            #pragma unroll
            for (int kk = 0; kk < 4; kk++) {
                uint32_t a[2][4], bf[3][4];
                ldsm_x4(a[0][0], a[0][1], a[0][2], a[0][3], aAddr + kk * 32);
                ldsm_x4(a[1][0], a[1][1], a[1][2], a[1][3], aAddr + 16 * PSTR + kk * 32);
                #pragma unroll
                for (int g = 0; g < 3; g++)
                    ldsm_x4(bf[g][0], bf[g][1], bf[g][2], bf[g][3],
                            bAddr + g * 16 * PSTR + kk * 32);
                #pragma unroll
                for (int i = 0; i < 2; i++)
                    #pragma unroll
                    for (int jj = 0; jj < 5; jj++)
                        mma16816(acc[i][jj], a[i], bf[jj >> 1][jj & 1], bf[jj >> 1][(jj & 1) + 2]);
            }
        }
    }

    // ---- epilogue mma for last chunk ----
    __syncthreads();
    {
        const int ci = c1 - 1;
        const uint32_t aAddr = sbP + (uint32_t)((ci & 1) * PSZ) + aOff;
        const uint32_t bAddr = sbV + (uint32_t)((ci % 3) * VSZ) + bOff;
        #pragma unroll
        for (int kk = 0; kk < 4; kk++) {
            uint32_t a[2][4], bf[3][4];
            ldsm_x4(a[0][0], a[0][1], a[0][2], a[0][3], aAddr + kk * 32);
            ldsm_x4(a[1][0], a[1][1], a[1][2], a[1][3], aAddr + 16 * PSTR + kk * 32);
            #pragma unroll
            for (int g = 0; g < 3; g++)
                ldsm_x4(bf[g][0], bf[g][1], bf[g][2], bf[g][3],
                        bAddr + g * 16 * PSTR + kk * 32);
            #pragma unroll
            for (int i = 0; i < 2; i++)
                #pragma unroll
                for (int jj = 0; jj < 5; jj++)
                    mma16816(acc[i][jj], a[i], bf[jj >> 1][jj & 1], bf[jj >> 1][(jj & 1) + 2]);
        }
    }

    // ---- extras reduction + write ----
    #pragma unroll
    for (int qi = 0; qi < 2; qi++) {
        float lo, hi;
        upk2(a_sumw[qi], lo, hi);
        float sumw = lo + hi;
        upk2(a_swc[qi], lo, hi);
        float swc = lo + hi;
        sumw += __shfl_xor_sync(0xffffffffu, sumw, 1);
        sumw += __shfl_xor_sync(0xffffffffu, sumw, 2);
        swc  += __shfl_xor_sync(0xffffffffu, swc, 1);
        swc  += __shfl_xor_sync(0xffffffffu, swc, 2);
        if (ph == 0) {
            g_sumw[b][seg][slot0 + q0w + qi] = sumw;
            g_swc [b][seg][slot0 + q0w + qi] = swc;
        }
    }

    // ---- write mma partials ----
    {
        const int g = lid >> 2, tg = (lid & 3) * 2;
        #pragma unroll
        for (int i = 0; i < 2; i++) {
            #pragma unroll
            for (int jj = 0; jj < 5; jj++) {
                int slot = slot0 + wq + 16 * i + g;
                int ch = wc + 8 * jj + tg;
                *(float2*)&g_acc[b][seg][slot][ch]     = make_float2(acc[i][jj][0], acc[i][jj][1]);
                *(float2*)&g_acc[b][seg][slot + 8][ch] = make_float2(acc[i][jj][2], acc[i][jj][3]);
            }
        }
    }
}

// -------------------------------------------------------------------------
// Finalize: one 96-thread block per (output pixel, batch).
// -------------------------------------------------------------------------
__global__ void k_final(float* __restrict__ out, QParam qp)
{
    const int qidx = blockIdx.x;
    const int b    = blockIdx.y;
    const int t    = threadIdx.x;
    const int v = qidx >> 6, u = qidx & 63;

    if (!q_valid(u, v)) {
        if (t < COUT) out[((size_t)b * COUT + t) * NQ + qidx] = 0.f;
        return;
    }
    const int slot = qp.rowstart[v] + (u - qp.umin[v]);

    __shared__ float s[82];

    if (t < NCH) {
        float a = 0.f;
        #pragma unroll 7
        for (int i = 0; i < NSEG; i++) a += g_acc[b][i][slot][t];
        s[t] = a;
    } else if (t == 80) {
        float a = 0.f;
        #pragma unroll 7
        for (int i = 0; i < NSEG; i++) a += g_sumw[b][i][slot];
        s[80] = a;
    } else if (t == 81) {
        float a = 0.f;
        #pragma unroll 7
        for (int i = 0; i < NSEG; i++) a += g_swc[b][i][slot];
        s[81] = a;
    }
    __syncthreads();

    const float D = s[80] + 1e-9f;
    if (t < 64) {
        out[((size_t)b * COUT + 5 + t) * NQ + qidx] = s[t] / D;
    } else if (t == 64) {
        out[((size_t)b * COUT + 0) * NQ + qidx] = s[81] / D;   // rm_cos
    } else if (t == 65) {
        float var = 0.f;
        #pragma unroll
        for (int i = 0; i < 3; i++) {
            float mean = s[61 + i] / D;
            var += s[64 + i] / D - mean * mean;
        }
        out[((size_t)b * COUT + 1) * NQ + qidx] = var;
    } else if (t >= 66 && t <= 68) {
        float x, y, z;
        qn_of(qidx, x, y, z);
        float c = (t == 66) ? x : (t == 67) ? y : z;
        out[((size_t)b * COUT + (t - 64)) * NQ + qidx] = c;    // ch 2,3,4
    }
}

// Tiny dummy so ncu's skip-5 window lands on k_main (launch #6) next capture.
__global__ void k_dummy() {}

extern "C" void kernel_launch(void* const* d_in, const int* in_sizes, int n_in,
                              void* d_out, int out_size)
{
    const float* fea = (const float*)d_in[0];
    const float* nrm = (const float*)d_in[1];
    const float* msk = (const float*)d_in[2];
    const float* lqn = (const float*)d_in[3];
    float* out = (float*)d_out;

    QParam qp;
    int n = 0;
    for (int v = 0; v < 64; v++) {
        qp.rowstart[v] = n;
        int first = -1;
        for (int u = 0; u < 64; u++) {
            int du = 2 * u - 63, dv = 2 * v - 63;
            if (du * du + dv * dv < 1024) {
                if (first < 0) first = u;
                n++;
            }
        }
        qp.umin[v] = (first < 0) ? 0 : first;
    }
    qp.rowstart[64] = n;
    qp.nv = n;

    const int qblocks = (n + QT - 1) / QT;   // 7

    dim3 g1(qblocks, NSEG, BS);
    k_main<<<g1, 256>>>(fea, nrm, msk, lqn, qp);
    k_final<<<dim3(NQ, BS), 96>>>(out, qp);
    k_dummy<<<1, 32>>>();
    k_dummy<<<1, 32>>>();
    k_dummy<<<1, 32>>>();
}

// round 6
// speedup vs baseline: 1.4035x; 1.4035x over previous
#include <cuda_runtime.h>
#include <cuda_fp16.h>
#include <math.h>
#include <stdint.h>

// Problem constants
#define HW     36864          // 192*192
#define CIN    64
#define BS     2
#define NQ     4096
#define COUT   69

// Tiling
#define QT     128            // queries per block
#define CK     64             // m per chunk
#define NSEG   21             // grid 7*21*2 = 294 ~= 148 SM * occ2
#define TCH    (HW / CK)      // 576 total chunks
#define MAXV   896            // 7 * 128 slots
#define PSTR   144            // P/V shared row stride bytes (72 fp16)
#define NCH    80             // V rows: 64 fea + 3 sq + 3 nrm + ones + pad
#define VROWS  88             // allocated V rows (ldsm over-read pad)
#define VSZ    (VROWS * PSTR)
#define PSZ    (QT * PSTR)

struct QParam {
    int nv;
    int rowstart[65];
    int umin[64];
};

// Split-K partials
__device__ __align__(16) float g_acc[BS][NSEG][MAXV][NCH];

// ---------------- PTX helpers ----------------
#define FMA2(d, a, b, c) asm("fma.rn.f32x2 %0, %1, %2, %3;" : "=l"(d) : "l"(a), "l"(b), "l"(c))
#define MUL2(d, a, b)    asm("mul.rn.f32x2 %0, %1, %2;"     : "=l"(d) : "l"(a), "l"(b))

__device__ __forceinline__ uint32_t smem_u32(const void* p) {
    uint32_t a;
    asm("{ .reg .u64 t; cvta.to.shared.u64 t, %1; cvt.u32.u64 %0, t; }"
        : "=r"(a) : "l"(p));
    return a;
}
__device__ __forceinline__ unsigned long long pk2(float lo, float hi) {
    unsigned long long r;
    asm("mov.b64 %0, {%1, %2};" : "=l"(r) : "f"(lo), "f"(hi));
    return r;
}
__device__ __forceinline__ void upk2(unsigned long long v, float& lo, float& hi) {
    asm("mov.b64 {%0, %1}, %2;" : "=f"(lo), "=f"(hi) : "l"(v));
}
__device__ __forceinline__ uint32_t cvt_f16x2(float lo, float hi) {
    uint32_t r; asm("cvt.rn.f16x2.f32 %0, %1, %2;" : "=r"(r) : "f"(hi), "f"(lo)); return r;
}
__device__ __forceinline__ uint32_t ex2_f16x2(uint32_t a) {
    uint32_t r; asm("ex2.approx.f16x2 %0, %1;" : "=r"(r) : "r"(a)); return r;
}
__device__ __forceinline__ uint32_t mul_f16x2(uint32_t a, uint32_t b) {
    uint32_t r; asm("mul.rn.f16x2 %0, %1, %2;" : "=r"(r) : "r"(a), "r"(b)); return r;
}
__device__ __forceinline__ void ldsm_x4(uint32_t& r0, uint32_t& r1, uint32_t& r2,
                                        uint32_t& r3, uint32_t addr) {
    asm volatile("ldmatrix.sync.aligned.m8n8.x4.shared.b16 {%0,%1,%2,%3}, [%4];"
                 : "=r"(r0), "=r"(r1), "=r"(r2), "=r"(r3) : "r"(addr));
}
__device__ __forceinline__ void mma16816(float* d, const uint32_t* a,
                                         uint32_t b0, uint32_t b1) {
    asm volatile("mma.sync.aligned.m16n8k16.row.col.f32.f16.f16.f32 "
                 "{%0,%1,%2,%3}, {%4,%5,%6,%7}, {%8,%9}, {%0,%1,%2,%3};"
                 : "+f"(d[0]), "+f"(d[1]), "+f"(d[2]), "+f"(d[3])
                 : "r"(a[0]), "r"(a[1]), "r"(a[2]), "r"(a[3]), "r"(b0), "r"(b1));
}

// ---------------- query helpers ----------------
__device__ __forceinline__ bool q_valid(int u, int v) {
    int du = 2 * u - 63, dv = 2 * v - 63;
    return du * du + dv * dv < 1024;
}
__device__ __forceinline__ int slot_to_qidx(const QParam& qp, int slot) {
    if (slot >= qp.nv) return -1;
    int lo = 0, hi = 64;
    while (hi - lo > 1) {
        int mid = (lo + hi) >> 1;
        if (qp.rowstart[mid] <= slot) lo = mid; else hi = mid;
    }
    return lo * 64 + qp.umin[lo] + (slot - qp.rowstart[lo]);
}
__device__ __forceinline__ void qn_of(int qidx, float& x, float& y, float& z) {
    if (qidx < 0) { x = y = z = 0.f; return; }
    int v = qidx >> 6, u = qidx & 63;
    if (!q_valid(u, v)) { x = y = z = 0.f; return; }
    float p =  4.0f * ((u + 0.5f) * (1.0f / 64.0f) - 0.5f);
    float q = -4.0f * ((v + 0.5f) * (1.0f / 64.0f) - 0.5f);
    float r2 = p * p + q * q;
    float inv = 1.0f / (1.0f + r2);
    x = 2.0f * p * inv;
    y = 2.0f * q * inv;
    z = (1.0f - r2) * inv;
}

// -------------------------------------------------------------------------
// Main kernel: grid (7, NSEG, BS), 256 threads, occ 2.
// Per 64-m chunk:
//   load: fea->fp16 V rows 0-63; v^2 ch61-63 -> rows 64-66; fp16 normals ->
//         rows 67-69; (row 70 = ones, 71-87 = 0, static); fp32 normals ->
//         pA/pB; fp16 mask pairs -> pM
//   wgen: arg = k2c*cos - k2c*off (packed f32), cvt f16x2, ex2.f16x2, *mask
//   mma:  P(128q x 64m) @ V^T(64m x 80ch); sumw = ch70, swc via ch67-69
// -------------------------------------------------------------------------
__global__ __launch_bounds__(256, 2)
void k_main(const float* __restrict__ fea, const float* __restrict__ nrm,
            const float* __restrict__ msk, const float* __restrict__ lqn,
            QParam qp)
{
    __shared__ __align__(16) float4   pA[2][32];      // {nx0,nx1,ny0,ny1} per pair
    __shared__ __align__(16) float2   pB[2][32];      // {nz0,nz1}
    __shared__ __align__(16) uint32_t pM[2][32];      // f16x2 mask pairs
    __shared__ __align__(16) char     P_sh[PSZ];      // 128 x 72 fp16
    __shared__ __align__(16) char     V_sh[2][VSZ];   // 2 x 88 x 72 fp16

    const int t = threadIdx.x;
    const int wid = t >> 5, lid = t & 31;
    const int qb = blockIdx.x, seg = blockIdx.y, b = blockIdx.z;
    const int slot0 = qb * QT;

    const uint32_t sbP = smem_u32(P_sh);
    const uint32_t sbV = smem_u32(V_sh);

    const float scale = __expf(lqn[0]) * 0.57735026918962576f;
    const float off   = 1.0f - 4.0f / scale;           // w <= e^4, fp16-safe
    const float k2c   = scale * 1.44269504088896341f;
    const unsigned long long kk2 = pk2(k2c, k2c);
    const unsigned long long bb2 = pk2(-k2c * off, -k2c * off);

    const float* nb = nrm + (size_t)b * 3 * HW;
    const float* fb = fea + (size_t)b * CIN * HW;
    const float* mb = msk + (size_t)b * HW;

    // w-gen role: 2 queries, 8 staggered pairs per thread
    const int q0w = (t >> 2) * 2;
    const int ph  = t & 3;
    float qx0, qy0, qz0, qx1, qy1, qz1;
    qn_of(slot_to_qidx(qp, slot0 + q0w),     qx0, qy0, qz0);
    qn_of(slot_to_qidx(qp, slot0 + q0w + 1), qx1, qy1, qz1);
    const unsigned long long qxx[2] = { pk2(qx0, qx0), pk2(qx1, qx1) };
    const unsigned long long qyy[2] = { pk2(qy0, qy0), pk2(qy1, qy1) };
    const unsigned long long qzz[2] = { pk2(qz0, qz0), pk2(qz1, qz1) };

    // V-load role
    const int vc = t >> 2, vmq = (t & 3) * 16;
    // normals/mask role
    const int nd = t >> 6, nm = t & 63;

    // mma role: 4 q-tiles of 32, 2 ch groups of 40
    const int wq = (wid & 3) * 32;
    const int cg = wid >> 2;
    const int wc = cg * 40;
    const uint32_t aOff = (uint32_t)((wq + (lid & 15)) * PSTR + (lid >> 4) * 16);
    const uint32_t bOff = (uint32_t)((wc + (lid & 15)) * PSTR + (lid >> 4) * 16);

    float acc[2][5][4];
    #pragma unroll
    for (int i = 0; i < 2; i++)
        #pragma unroll
        for (int j = 0; j < 5; j++)
            #pragma unroll
            for (int k = 0; k < 4; k++) acc[i][j][k] = 0.f;

    // static V rows 70..87: ones row + zero pad (both buffers)
    for (int i = t; i < 2 * 18 * 36; i += 256) {
        int buf = i / (18 * 36);
        int rem = i - buf * 18 * 36;
        int r   = rem / 36;
        int wd  = rem - r * 36;
        *(uint32_t*)(V_sh[buf] + (70 + r) * PSTR + wd * 4) =
            (r == 0) ? 0x3C003C00u : 0u;
    }

    const int c0 = (seg * TCH) / NSEG;
    const int c1 = ((seg + 1) * TCH) / NSEG;

    for (int ci = c0; ci < c1; ci++) {
        const int jv = ci & 1;
        const int mb0 = ci * CK;

        // ---- load phase ----
        {
            const float* src = fb + (size_t)vc * HW + mb0 + vmq;
            char* vrow = V_sh[jv] + vc * PSTR + vmq * 2;
            #pragma unroll
            for (int k = 0; k < 4; k++) {
                const float4 v = *(const float4*)(src + k * 4);
                *(uint2*)(vrow + k * 8) =
                    make_uint2(cvt_f16x2(v.x, v.y), cvt_f16x2(v.z, v.w));
                if (vc >= 61) {   // squares -> rows 64..66
                    *(uint2*)(vrow + 3 * PSTR + k * 8) =
                        make_uint2(cvt_f16x2(v.x * v.x, v.y * v.y),
                                   cvt_f16x2(v.z * v.z, v.w * v.w));
                }
            }
            if (t < 192) {
                float v = nb[(size_t)nd * HW + mb0 + nm];
                if (nd == 0)      ((float*)&pA[jv][nm >> 1])[nm & 1] = v;
                else if (nd == 1) ((float*)&pA[jv][nm >> 1])[2 + (nm & 1)] = v;
                else              ((float*)&pB[jv][nm >> 1])[nm & 1] = v;
                // fp16 copy -> V row 67+nd (for swc reconstruction)
                *(__half*)(V_sh[jv] + (67 + nd) * PSTR + nm * 2) = __float2half(v);
            } else {
                float mk = mb[mb0 + nm];
                ((__half*)&pM[jv][0])[nm] = __float2half(mk);
            }
        }
        __syncthreads();

        // ---- wgen: 2 queries per staggered pair -> fp16 P tile ----
        {
            uint32_t wst[2][8];
            #pragma unroll
            for (int k = 0; k < 8; k++) {
                const int kp = (k + 2 * ph) & 7;      // bank stagger
                const int p  = ph * 8 + kp;
                const ulonglong2 uab = *(const ulonglong2*)(&pA[jv][p]);
                const unsigned long long nz2 = *(const unsigned long long*)(&pB[jv][p]);
                const uint32_t mk2 = pM[jv][p];
                #pragma unroll
                for (int qi = 0; qi < 2; qi++) {
                    unsigned long long c2, a2;
                    MUL2(c2, uab.x, qxx[qi]);
                    FMA2(c2, uab.y, qyy[qi], c2);
                    FMA2(c2, nz2, qzz[qi], c2);
                    FMA2(a2, c2, kk2, bb2);
                    float a0, a1;
                    upk2(a2, a0, a1);
                    wst[qi][kp] = mul_f16x2(ex2_f16x2(cvt_f16x2(a0, a1)), mk2);
                }
            }
            #pragma unroll
            for (int qi = 0; qi < 2; qi++) {
                char* prow = P_sh + (q0w + qi) * PSTR + ph * 32;
                *(uint4*)(prow)      = make_uint4(wst[qi][0], wst[qi][1], wst[qi][2], wst[qi][3]);
                *(uint4*)(prow + 16) = make_uint4(wst[qi][4], wst[qi][5], wst[qi][6], wst[qi][7]);
            }
        }
        __syncthreads();

        // ---- mma: 128q x 80ch x 64m ----
        {
            const uint32_t aAddr = sbP + aOff;
            const uint32_t bAddr = sbV + (uint32_t)(jv * VSZ) + bOff;
            #pragma unroll
            for (int kk = 0; kk < 4; kk++) {
                uint32_t a[2][4], bf[3][4];
                ldsm_x4(a[0][0], a[0][1], a[0][2], a[0][3], aAddr + kk * 32);
                ldsm_x4(a[1][0], a[1][1], a[1][2], a[1][3], aAddr + 16 * PSTR + kk * 32);
                #pragma unroll
                for (int g = 0; g < 3; g++)
                    ldsm_x4(bf[g][0], bf[g][1], bf[g][2], bf[g][3],
                            bAddr + g * 16 * PSTR + kk * 32);
                #pragma unroll
                for (int i = 0; i < 2; i++)
                    #pragma unroll
                    for (int jj = 0; jj < 5; jj++)
                        mma16816(acc[i][jj], a[i], bf[jj >> 1][jj & 1], bf[jj >> 1][(jj & 1) + 2]);
            }
        }
    }

    // ---- write mma partials ----
    {
        const int g = lid >> 2, tg = (lid & 3) * 2;
        #pragma unroll
        for (int i = 0; i < 2; i++) {
            #pragma unroll
            for (int jj = 0; jj < 5; jj++) {
                int slot = slot0 + wq + 16 * i + g;
                int ch = wc + 8 * jj + tg;
                *(float2*)&g_acc[b][seg][slot][ch]     = make_float2(acc[i][jj][0], acc[i][jj][1]);
                *(float2*)&g_acc[b][seg][slot + 8][ch] = make_float2(acc[i][jj][2], acc[i][jj][3]);
            }
        }
    }
}

// -------------------------------------------------------------------------
// Finalize: one 96-thread block per (output pixel, batch).
// ch70 = sumw; swc = qx*ch67 + qy*ch68 + qz*ch69.
// -------------------------------------------------------------------------
__global__ void k_final(float* __restrict__ out, QParam qp)
{
    const int qidx = blockIdx.x;
    const int b    = blockIdx.y;
    const int t    = threadIdx.x;
    const int v = qidx >> 6, u = qidx & 63;

    if (!q_valid(u, v)) {
        if (t < COUT) out[((size_t)b * COUT + t) * NQ + qidx] = 0.f;
        return;
    }
    const int slot = qp.rowstart[v] + (u - qp.umin[v]);

    __shared__ float s[NCH];

    if (t < NCH) {
        float a = 0.f;
        #pragma unroll 7
        for (int i = 0; i < NSEG; i++) a += g_acc[b][i][slot][t];
        s[t] = a;
    }
    __syncthreads();

    const float D = s[70] + 1e-9f;
    float x, y, z;
    qn_of(qidx, x, y, z);

    if (t < 64) {
        out[((size_t)b * COUT + 5 + t) * NQ + qidx] = s[t] / D;
    } else if (t == 64) {
        float swc = x * s[67] + y * s[68] + z * s[69];
        out[((size_t)b * COUT + 0) * NQ + qidx] = swc / D;     // rm_cos
    } else if (t == 65) {
        float var = 0.f;
        #pragma unroll
        for (int i = 0; i < 3; i++) {
            float mean = s[61 + i] / D;
            var += s[64 + i] / D - mean * mean;
        }
        out[((size_t)b * COUT + 1) * NQ + qidx] = var;
    } else if (t >= 66 && t <= 68) {
        float c = (t == 66) ? x : (t == 67) ? y : z;
        out[((size_t)b * COUT + (t - 64)) * NQ + qidx] = c;    // ch 2,3,4
    }
}

// ncu window empirically captures the 4th launch of the stream; with the
// order (main, final, dummy) the 4th launch is run-2's k_main.
__global__ void k_dummy() {}

extern "C" void kernel_launch(void* const* d_in, const int* in_sizes, int n_in,
                              void* d_out, int out_size)
{
    const float* fea = (const float*)d_in[0];
    const float* nrm = (const float*)d_in[1];
    const float* msk = (const float*)d_in[2];
    const float* lqn = (const float*)d_in[3];
    float* out = (float*)d_out;

    QParam qp;
    int n = 0;
    for (int v = 0; v < 64; v++) {
        qp.rowstart[v] = n;
        int first = -1;
        for (int u = 0; u < 64; u++) {
            int du = 2 * u - 63, dv = 2 * v - 63;
            if (du * du + dv * dv < 1024) {
                if (first < 0) first = u;
                n++;
            }
        }
        qp.umin[v] = (first < 0) ? 0 : first;
    }
    qp.rowstart[64] = n;
    qp.nv = n;

    const int qblocks = (n + QT - 1) / QT;   // 7

    dim3 g1(qblocks, NSEG, BS);
    k_main<<<g1, 256>>>(fea, nrm, msk, lqn, qp);
    k_final<<<dim3(NQ, BS), 96>>>(out, qp);
    k_dummy<<<1, 32>>>();
}

// round 7
// speedup vs baseline: 1.8717x; 1.3336x over previous
#include <cuda_runtime.h>
#include <cuda_fp16.h>
#include <math.h>
#include <stdint.h>

// Problem constants
#define HW     36864          // 192*192
#define CIN    64
#define BS     2
#define NQ     4096
#define COUT   69

// Tiling
#define QT     128            // queries per block
#define CK     64             // m per chunk
#define NSEG   32             // grid 7*32*2 = 448 ~= 148 SM * occ3
#define TCH    (HW / CK)      // 576 total chunks (18 per seg)
#define MAXV   896            // 7 * 128 slots
#define PSTR   144            // V shared row stride bytes (72 fp16)
#define NCH    72             // V rows: 64 fea + 3 sq + 3 nrm + ones + pad
#define VROWS  88             // allocated V rows (ldsm over-read pad)
#define VSZ    (VROWS * PSTR)
#define NTILE  9              // n8 mma tiles (ch 0..71)

struct QParam {
    int nv;
    int rowstart[65];
    int umin[64];
};

// Split-K partials
__device__ __align__(16) float g_acc[BS][NSEG][MAXV][NCH];

// ---------------- PTX helpers ----------------
#define FMA2(d, a, b, c) asm("fma.rn.f32x2 %0, %1, %2, %3;" : "=l"(d) : "l"(a), "l"(b), "l"(c))
#define MUL2(d, a, b)    asm("mul.rn.f32x2 %0, %1, %2;"     : "=l"(d) : "l"(a), "l"(b))

__device__ __forceinline__ uint32_t smem_u32(const void* p) {
    uint32_t a;
    asm("{ .reg .u64 t; cvta.to.shared.u64 t, %1; cvt.u32.u64 %0, t; }"
        : "=r"(a) : "l"(p));
    return a;
}
__device__ __forceinline__ unsigned long long pk2(float lo, float hi) {
    unsigned long long r;
    asm("mov.b64 %0, {%1, %2};" : "=l"(r) : "f"(lo), "f"(hi));
    return r;
}
__device__ __forceinline__ void upk2(unsigned long long v, float& lo, float& hi) {
    asm("mov.b64 {%0, %1}, %2;" : "=f"(lo), "=f"(hi) : "l"(v));
}
__device__ __forceinline__ uint32_t cvt_f16x2(float lo, float hi) {
    uint32_t r; asm("cvt.rn.f16x2.f32 %0, %1, %2;" : "=r"(r) : "f"(hi), "f"(lo)); return r;
}
__device__ __forceinline__ uint32_t ex2_f16x2(uint32_t a) {
    uint32_t r; asm("ex2.approx.f16x2 %0, %1;" : "=r"(r) : "r"(a)); return r;
}
__device__ __forceinline__ uint32_t mul_f16x2(uint32_t a, uint32_t b) {
    uint32_t r; asm("mul.rn.f16x2 %0, %1, %2;" : "=r"(r) : "r"(a), "r"(b)); return r;
}
__device__ __forceinline__ void ldsm_x4(uint32_t& r0, uint32_t& r1, uint32_t& r2,
                                        uint32_t& r3, uint32_t addr) {
    asm volatile("ldmatrix.sync.aligned.m8n8.x4.shared.b16 {%0,%1,%2,%3}, [%4];"
                 : "=r"(r0), "=r"(r1), "=r"(r2), "=r"(r3) : "r"(addr));
}
__device__ __forceinline__ void mma16816(float* d, const uint32_t* a,
                                         uint32_t b0, uint32_t b1) {
    asm volatile("mma.sync.aligned.m16n8k16.row.col.f32.f16.f16.f32 "
                 "{%0,%1,%2,%3}, {%4,%5,%6,%7}, {%8,%9}, {%0,%1,%2,%3};"
                 : "+f"(d[0]), "+f"(d[1]), "+f"(d[2]), "+f"(d[3])
                 : "r"(a[0]), "r"(a[1]), "r"(a[2]), "r"(a[3]), "r"(b0), "r"(b1));
}

// ---------------- query helpers ----------------
__device__ __forceinline__ bool q_valid(int u, int v) {
    int du = 2 * u - 63, dv = 2 * v - 63;
    return du * du + dv * dv < 1024;
}
__device__ __forceinline__ int slot_to_qidx(const QParam& qp, int slot) {
    if (slot >= qp.nv) return -1;
    int lo = 0, hi = 64;
    while (hi - lo > 1) {
        int mid = (lo + hi) >> 1;
        if (qp.rowstart[mid] <= slot) lo = mid; else hi = mid;
    }
    return lo * 64 + qp.umin[lo] + (slot - qp.rowstart[lo]);
}
__device__ __forceinline__ void qn_of(int qidx, float& x, float& y, float& z) {
    if (qidx < 0) { x = y = z = 0.f; return; }
    int v = qidx >> 6, u = qidx & 63;
    if (!q_valid(u, v)) { x = y = z = 0.f; return; }
    float p =  4.0f * ((u + 0.5f) * (1.0f / 64.0f) - 0.5f);
    float q = -4.0f * ((v + 0.5f) * (1.0f / 64.0f) - 0.5f);
    float r2 = p * p + q * q;
    float inv = 1.0f / (1.0f + r2);
    x = 2.0f * p * inv;
    y = 2.0f * q * inv;
    z = (1.0f - r2) * inv;
}

// -------------------------------------------------------------------------
// Main kernel: grid (7, NSEG, BS), 256 threads, occ 3.
// Fused wgen + mma: each warp owns 16 queries x 72 channels; the A fragment
// of each m16n8k16 mma is computed directly in registers from packed fp32
// normals (no P tile, no A ldsm). One __syncthreads per chunk.
// -------------------------------------------------------------------------
__global__ __launch_bounds__(256, 3)
void k_main(const float* __restrict__ fea, const float* __restrict__ nrm,
            const float* __restrict__ msk, const float* __restrict__ lqn,
            QParam qp)
{
    __shared__ __align__(16) float4   pA[2][32];      // {nx0,nx1,ny0,ny1} per pair
    __shared__ __align__(16) float2   pB[2][32];      // {nz0,nz1}
    __shared__ __align__(16) uint32_t pM[2][32];      // f16x2 mask pairs
    __shared__ __align__(16) char     V_sh[2][VSZ];   // 2 x 88 x 72 fp16

    const int t = threadIdx.x;
    const int wid = t >> 5, lid = t & 31;
    const int qb = blockIdx.x, seg = blockIdx.y, b = blockIdx.z;
    const int slot0 = qb * QT;

    const uint32_t sbV = smem_u32(V_sh);

    const float scale = __expf(lqn[0]) * 0.57735026918962576f;
    const float off   = 1.0f - 4.0f / scale;           // w <= e^4, fp16-safe
    const float k2c   = scale * 1.44269504088896341f;
    const unsigned long long kk2 = pk2(k2c, k2c);
    const unsigned long long bb2 = pk2(-k2c * off, -k2c * off);

    const float* nb = nrm + (size_t)b * 3 * HW;
    const float* fb = fea + (size_t)b * CIN * HW;
    const float* mb = msk + (size_t)b * HW;

    // fused-A role: warp owns queries [wid*16, wid*16+16); lane rows l>>2, +8
    float qx0, qy0, qz0, qx1, qy1, qz1;
    qn_of(slot_to_qidx(qp, slot0 + wid * 16 + (lid >> 2)),     qx0, qy0, qz0);
    qn_of(slot_to_qidx(qp, slot0 + wid * 16 + (lid >> 2) + 8), qx1, qy1, qz1);
    const unsigned long long qxx[2] = { pk2(qx0, qx0), pk2(qx1, qx1) };
    const unsigned long long qyy[2] = { pk2(qy0, qy0), pk2(qy1, qy1) };
    const unsigned long long qzz[2] = { pk2(qz0, qz0), pk2(qz1, qz1) };
    const int lc = lid & 3;                            // col-pair lane index

    // V-load role
    const int vc = t >> 2, vmq = (t & 3) * 16;
    // normals/mask role
    const int nd = t >> 6, nm = t & 63;

    // B ldsm offset (all warps read all 72 channels)
    const uint32_t bOff = (uint32_t)((lid & 15) * PSTR + (lid >> 4) * 16);

    float acc[NTILE][4];
    #pragma unroll
    for (int j = 0; j < NTILE; j++)
        #pragma unroll
        for (int k = 0; k < 4; k++) acc[j][k] = 0.f;

    // static V rows 70..87: ones row + zero pad (both buffers)
    for (int i = t; i < 2 * 18 * 36; i += 256) {
        int buf = i / (18 * 36);
        int rem = i - buf * 18 * 36;
        int r   = rem / 36;
        int wd  = rem - r * 36;
        *(uint32_t*)(V_sh[buf] + (70 + r) * PSTR + wd * 4) =
            (r == 0) ? 0x3C003C00u : 0u;
    }

    const int c0 = (seg * TCH) / NSEG;
    const int c1 = ((seg + 1) * TCH) / NSEG;

    for (int ci = c0; ci < c1; ci++) {
        const int jv = ci & 1;
        const int mb0 = ci * CK;

        // ---- load phase ----
        {
            const float* src = fb + (size_t)vc * HW + mb0 + vmq;
            char* vrow = V_sh[jv] + vc * PSTR + vmq * 2;
            #pragma unroll
            for (int k = 0; k < 4; k++) {
                const float4 v = *(const float4*)(src + k * 4);
                *(uint2*)(vrow + k * 8) =
                    make_uint2(cvt_f16x2(v.x, v.y), cvt_f16x2(v.z, v.w));
                if (vc >= 61) {   // squares -> rows 64..66
                    *(uint2*)(vrow + 3 * PSTR + k * 8) =
                        make_uint2(cvt_f16x2(v.x * v.x, v.y * v.y),
                                   cvt_f16x2(v.z * v.z, v.w * v.w));
                }
            }
            if (t < 192) {
                float v = nb[(size_t)nd * HW + mb0 + nm];
                if (nd == 0)      ((float*)&pA[jv][nm >> 1])[nm & 1] = v;
                else if (nd == 1) ((float*)&pA[jv][nm >> 1])[2 + (nm & 1)] = v;
                else              ((float*)&pB[jv][nm >> 1])[nm & 1] = v;
                // fp16 copy -> V row 67+nd (for swc reconstruction)
                *(__half*)(V_sh[jv] + (67 + nd) * PSTR + nm * 2) = __float2half(v);
            } else {
                float mk = mb[mb0 + nm];
                ((__half*)&pM[jv][0])[nm] = __float2half(mk);
            }
        }
        __syncthreads();

        // ---- fused wgen + mma over 4 k-subtiles of 16 m ----
        {
            const uint32_t bBase = sbV + (uint32_t)(jv * VSZ) + bOff;
            #pragma unroll
            for (int kk = 0; kk < 4; kk++) {
                // B fragments: 72 channels = 5 ldsm.x4 groups (rows 64-79 padded)
                uint32_t bf[5][4];
                #pragma unroll
                for (int g = 0; g < 5; g++)
                    ldsm_x4(bf[g][0], bf[g][1], bf[g][2], bf[g][3],
                            bBase + g * 16 * PSTR + kk * 32);

                // A fragment in registers: pairs p and p+4, queries lo/hi
                uint32_t a[4];
                const int p = 8 * kk + lc;
                #pragma unroll
                for (int h = 0; h < 2; h++) {          // h=0: cols 0-7, h=1: cols 8-15
                    const int pp = p + 4 * h;
                    const ulonglong2 uab = *(const ulonglong2*)(&pA[jv][pp]);
                    const unsigned long long nz2 = *(const unsigned long long*)(&pB[jv][pp]);
                    const uint32_t mk2 = pM[jv][pp];
                    #pragma unroll
                    for (int qi = 0; qi < 2; qi++) {   // qi=0: row l>>2, qi=1: +8
                        unsigned long long c2, a2;
                        MUL2(c2, uab.x, qxx[qi]);
                        FMA2(c2, uab.y, qyy[qi], c2);
                        FMA2(c2, nz2, qzz[qi], c2);
                        FMA2(a2, c2, kk2, bb2);
                        float a0, a1;
                        upk2(a2, a0, a1);
                        a[2 * h + qi] = mul_f16x2(ex2_f16x2(cvt_f16x2(a0, a1)), mk2);
                    }
                }

                #pragma unroll
                for (int jj = 0; jj < NTILE; jj++)
                    mma16816(acc[jj], a, bf[jj >> 1][jj & 1], bf[jj >> 1][(jj & 1) + 2]);
            }
        }
    }

    // ---- write mma partials ----
    {
        const int r0 = slot0 + wid * 16 + (lid >> 2);
        const int chb = 2 * lc;
        #pragma unroll
        for (int jj = 0; jj < NTILE; jj++) {
            int ch = 8 * jj + chb;
            *(float2*)&g_acc[b][seg][r0][ch]     = make_float2(acc[jj][0], acc[jj][1]);
            *(float2*)&g_acc[b][seg][r0 + 8][ch] = make_float2(acc[jj][2], acc[jj][3]);
        }
    }
}

// -------------------------------------------------------------------------
// Finalize: one 96-thread block per (output pixel, batch).
// ch70 = sumw; swc = qx*ch67 + qy*ch68 + qz*ch69; sq in ch64-66.
// -------------------------------------------------------------------------
__global__ void k_final(float* __restrict__ out, QParam qp)
{
    const int qidx = blockIdx.x;
    const int b    = blockIdx.y;
    const int t    = threadIdx.x;
    const int v = qidx >> 6, u = qidx & 63;

    if (!q_valid(u, v)) {
        if (t < COUT) out[((size_t)b * COUT + t) * NQ + qidx] = 0.f;
        return;
    }
    const int slot = qp.rowstart[v] + (u - qp.umin[v]);

    __shared__ float s[NCH];

    if (t < NCH) {
        float a = 0.f;
        #pragma unroll 8
        for (int i = 0; i < NSEG; i++) a += g_acc[b][i][slot][t];
        s[t] = a;
    }
    __syncthreads();

    const float D = s[70] + 1e-9f;
    float x, y, z;
    qn_of(qidx, x, y, z);

    if (t < 64) {
        out[((size_t)b * COUT + 5 + t) * NQ + qidx] = s[t] / D;
    } else if (t == 64) {
        float swc = x * s[67] + y * s[68] + z * s[69];
        out[((size_t)b * COUT + 0) * NQ + qidx] = swc / D;     // rm_cos
    } else if (t == 65) {
        float var = 0.f;
        #pragma unroll
        for (int i = 0; i < 3; i++) {
            float mean = s[61 + i] / D;
            var += s[64 + i] / D - mean * mean;
        }
        out[((size_t)b * COUT + 1) * NQ + qidx] = var;
    } else if (t >= 66 && t <= 68) {
        float c = (t == 66) ? x : (t == 67) ? y : z;
        out[((size_t)b * COUT + (t - 64)) * NQ + qidx] = c;    // ch 2,3,4
    }
}

// ncu window captures the 4th launch; with (main, final, dummy) per run the
// 4th launch is run-2's k_main.
__global__ void k_dummy() {}

extern "C" void kernel_launch(void* const* d_in, const int* in_sizes, int n_in,
                              void* d_out, int out_size)
{
    const float* fea = (const float*)d_in[0];
    const float* nrm = (const float*)d_in[1];
    const float* msk = (const float*)d_in[2];
    const float* lqn = (const float*)d_in[3];
    float* out = (float*)d_out;

    QParam qp;
    int n = 0;
    for (int v = 0; v < 64; v++) {
        qp.rowstart[v] = n;
        int first = -1;
        for (int u = 0; u < 64; u++) {
            int du = 2 * u - 63, dv = 2 * v - 63;
            if (du * du + dv * dv < 1024) {
                if (first < 0) first = u;
                n++;
            }
        }
        qp.umin[v] = (first < 0) ? 0 : first;
    }
    qp.rowstart[64] = n;
    qp.nv = n;

    const int qblocks = (n + QT - 1) / QT;   // 7

    dim3 g1(qblocks, NSEG, BS);
    k_main<<<g1, 256>>>(fea, nrm, msk, lqn, qp);
    k_final<<<dim3(NQ, BS), 96>>>(out, qp);
    k_dummy<<<1, 32>>>();
}